// round 9
// baseline (speedup 1.0000x reference)
#include <cuda_runtime.h>
#include <cuda_fp16.h>
#include <cstdint>

// CategorySpecificLinear, round 9:
//  pass 0: flag used categories
//  pass 1: convert used-category W slices to fp16 scratch
//  pass 2: convert x to fp16 scratch
//  pass 3: GEMM: cp.async fp16 3-stage ring (TK=64) + ldmatrix + mma m16n8k16,
//          grid ordered bn-outermost for L2-resident W.
// out[b] = x[b] @ W[cat_ids[b]] + bias[cat_ids[b]]

#define B_DIM 64
#define T_DIM 256
#define K_DIM 1024
#define N_DIM 2048
#define NCAT  32

#define TM 128
#define TN 128
#define TK 64
#define STAGES (K_DIM / TK)      // 16
#define NBUF 3
#define NTHREADS 128

// A tile: 128 rows x 64 k f16 = 128B/row (native SW128 line), swizzled.
#define A_STAGE_BYTES (128 * 128)            // 16384
// B tile: 64 k-rows x 128 n f16, row = 256B + 16B pad = 272B.
#define B_ROW_BYTES 272
#define B_STAGE_BYTES (64 * B_ROW_BYTES)     // 17408
#define STAGE_BYTES (A_STAGE_BYTES + B_STAGE_BYTES)  // 33792
#define SMEM_BYTES (NBUF * STAGE_BYTES)      // 101376 -> 2 CTAs/SM

__device__ __half g_xh[(size_t)B_DIM * T_DIM * K_DIM];   // 32 MiB
__device__ __half g_wh[(size_t)NCAT * K_DIM * N_DIM];    // 128 MiB
__device__ int    g_catflag[NCAT];

static __device__ __forceinline__ uint32_t sw(uint32_t b) { return b ^ ((b >> 3) & 0x70); }

static __device__ __forceinline__ uint32_t packh2(float lo, float hi) {
    uint32_t r;
    asm("cvt.rn.f16x2.f32 %0, %1, %2;" : "=r"(r) : "f"(hi), "f"(lo));
    return r;
}

static __device__ __forceinline__ void cpasync16(uint32_t dst, const void* src) {
    asm volatile("cp.async.cg.shared.global [%0], [%1], 16;" :: "r"(dst), "l"(src));
}

static __device__ __forceinline__ void ldsm_x4(uint32_t (&r)[4], uint32_t addr) {
    asm volatile("ldmatrix.sync.aligned.m8n8.x4.shared.b16 {%0,%1,%2,%3}, [%4];"
                 : "=r"(r[0]), "=r"(r[1]), "=r"(r[2]), "=r"(r[3]) : "r"(addr));
}
static __device__ __forceinline__ void ldsm_x4_trans(uint32_t (&r)[4], uint32_t addr) {
    asm volatile("ldmatrix.sync.aligned.m8n8.x4.trans.shared.b16 {%0,%1,%2,%3}, [%4];"
                 : "=r"(r[0]), "=r"(r[1]), "=r"(r[2]), "=r"(r[3]) : "r"(addr));
}

static __device__ __forceinline__ void mma_f16(float (&d)[4],
                                               const uint32_t (&a)[4],
                                               const uint32_t* b) {
    asm volatile(
        "mma.sync.aligned.m16n8k16.row.col.f32.f16.f16.f32 "
        "{%0,%1,%2,%3}, {%4,%5,%6,%7}, {%8,%9}, {%0,%1,%2,%3};"
        : "+f"(d[0]), "+f"(d[1]), "+f"(d[2]), "+f"(d[3])
        : "r"(a[0]), "r"(a[1]), "r"(a[2]), "r"(a[3]), "r"(b[0]), "r"(b[1]));
}

// ---------------- pass 0: flag used categories -------------------------------
__global__ void flag_cats(const int* __restrict__ cat_ids)
{
    int tid = threadIdx.x;
    if (tid < NCAT) g_catflag[tid] = 0;
    __syncthreads();
    if (tid < B_DIM) atomicOr(&g_catflag[cat_ids[tid]], 1);
}

// ---------------- pass 1: convert W (skip unused cats) ----------------------
__global__ void __launch_bounds__(256)
cvt_w(const float* __restrict__ W)
{
    const int cat = blockIdx.y;
    if (!g_catflag[cat]) return;
    const float* src = W + (size_t)cat * K_DIM * N_DIM;
    __half* dst = g_wh + (size_t)cat * K_DIM * N_DIM;
    const int n8 = (K_DIM * N_DIM) / 8;                 // 262144
    int i = blockIdx.x * blockDim.x + threadIdx.x;
    const int stride = gridDim.x * blockDim.x;
    for (; i < n8; i += stride) {
        float4 a = ((const float4*)src)[2 * i];
        float4 b = ((const float4*)src)[2 * i + 1];
        uint4 o;
        o.x = packh2(a.x, a.y);
        o.y = packh2(a.z, a.w);
        o.z = packh2(b.x, b.y);
        o.w = packh2(b.z, b.w);
        ((uint4*)dst)[i] = o;
    }
}

// ---------------- pass 2: convert x ------------------------------------------
__global__ void __launch_bounds__(256)
cvt_x(const float* __restrict__ x)
{
    const int n8 = (B_DIM * T_DIM * K_DIM) / 8;         // 2097152
    int i = blockIdx.x * blockDim.x + threadIdx.x;
    const int stride = gridDim.x * blockDim.x;
    for (; i < n8; i += stride) {
        float4 a = ((const float4*)x)[2 * i];
        float4 b = ((const float4*)x)[2 * i + 1];
        uint4 o;
        o.x = packh2(a.x, a.y);
        o.y = packh2(a.z, a.w);
        o.z = packh2(b.x, b.y);
        o.w = packh2(b.z, b.w);
        ((uint4*)g_xh)[i] = o;
    }
}

// ---------------- pass 3: GEMM ------------------------------------------------
__global__ void __launch_bounds__(NTHREADS, 2)
cat_linear_mma(const int* __restrict__ cat_ids,
               const float* __restrict__ bias,
               float* __restrict__ out)
{
    extern __shared__ char smraw[];
    const uint32_t smbase = (uint32_t)__cvta_generic_to_shared(smraw);

    const int tid  = threadIdx.x;
    const int wid  = tid >> 5;
    const int lane = tid & 31;
    const int wm   = wid >> 1;        // 0..1 (M half)
    const int wn   = wid & 1;         // 0..1 (N half)
    const int fr   = lane >> 2;       // 0..7
    const int fc   = lane & 3;        // 0..3

    // bn outermost (z), batch innermost (x): co-resident CTAs share one bn
    // column -> W working set ~7 MB, L2-resident across all batches.
    const int batch = blockIdx.x;     // 0..63
    const int bm    = blockIdx.y;     // 0..1
    const int bn    = blockIdx.z;     // 0..15
    const int n0    = bn * TN;
    const int cat   = cat_ids[batch];

    const __half* Ap = g_xh + (size_t)batch * T_DIM * K_DIM + (size_t)bm * TM * K_DIM;
    const __half* Bp = g_wh + (size_t)cat * K_DIM * N_DIM + n0;

    // cp.async maps (16B granules):
    // A: 1024 chunks = 128 rows x 8; thread i: f=tid+128i -> m=f>>3, c=f&7
    // B: 1024 chunks = 64 rows x 16; thread i: f=tid+128i -> k=f>>4, c=f&15
    // ldmatrix per-lane address components
    const int q_row = (lane & 7) + 8 * ((lane >> 3) & 1);
    const int q_hi  = (lane >> 4);
    const uint32_t a_pre = (uint32_t)((wm * 64 + q_row) * 128 + 16 * q_hi);
    const uint32_t b_pre = (uint32_t)(q_row * B_ROW_BYTES + (wn * 64 + 8 * q_hi) * 2);

    float acc[4][8][4];
#pragma unroll
    for (int m = 0; m < 4; m++)
#pragma unroll
        for (int n = 0; n < 8; n++)
#pragma unroll
            for (int j = 0; j < 4; j++) acc[m][n][j] = 0.f;

    auto issue_stage = [&](int s, int buf) {
        const uint32_t abase = smbase + (uint32_t)buf * STAGE_BYTES;
        const uint32_t bbase = abase + A_STAGE_BYTES;
        const int k0 = s * TK;
#pragma unroll
        for (int i = 0; i < 8; i++) {
            int f = tid + NTHREADS * i;
            int m = f >> 3, c = f & 7;
            cpasync16(abase + sw((uint32_t)m * 128u + (uint32_t)c * 16u),
                      Ap + (size_t)m * K_DIM + k0 + c * 8);
        }
#pragma unroll
        for (int i = 0; i < 8; i++) {
            int f = tid + NTHREADS * i;
            int k = f >> 4, c = f & 15;
            cpasync16(bbase + (uint32_t)k * B_ROW_BYTES + (uint32_t)c * 16u,
                      Bp + (size_t)(k0 + k) * N_DIM + c * 8);
        }
    };

    // prologue: 2 stages in flight
    issue_stage(0, 0);
    asm volatile("cp.async.commit_group;" ::: "memory");
    issue_stage(1, 1);
    asm volatile("cp.async.commit_group;" ::: "memory");

    for (int s = 0; s < STAGES; s++) {
        asm volatile("cp.async.wait_group 1;" ::: "memory");
        __syncthreads();

        // refill: buffer (s+2)%3 held stage s-1, done by all warps at barrier
        if (s + 2 < STAGES)
            issue_stage(s + 2, (s + 2) % NBUF);
        asm volatile("cp.async.commit_group;" ::: "memory");

        const uint32_t abase = smbase + (uint32_t)(s % NBUF) * STAGE_BYTES;
        const uint32_t bbase = abase + A_STAGE_BYTES;

#pragma unroll
        for (int kb = 0; kb < TK; kb += 16) {
            uint32_t af[4][4], bf[4][4];
#pragma unroll
            for (int mt = 0; mt < 4; mt++)
                ldsm_x4(af[mt], abase + sw(a_pre + (uint32_t)(mt * 16 * 128) + (uint32_t)(kb * 2)));
#pragma unroll
            for (int g = 0; g < 4; g++)
                ldsm_x4_trans(bf[g], bbase + b_pre + (uint32_t)(kb * B_ROW_BYTES) + (uint32_t)(g * 32));
#pragma unroll
            for (int m = 0; m < 4; m++)
#pragma unroll
                for (int n = 0; n < 8; n++)
                    mma_f16(acc[m][n], af[m], &bf[n >> 1][(n & 1) * 2]);
        }
    }

    // epilogue: add bias, store
    {
        const float* brow = bias + (size_t)cat * N_DIM;
        float* obase = out + (size_t)batch * T_DIM * N_DIM;
#pragma unroll
        for (int m = 0; m < 4; m++) {
            int row = bm * TM + wm * 64 + m * 16 + fr;
#pragma unroll
            for (int n = 0; n < 8; n++) {
                int col = n0 + wn * 64 + n * 8 + fc * 2;
                float2 bv = *(const float2*)(brow + col);
                float2 o0, o1;
                o0.x = acc[m][n][0] + bv.x;
                o0.y = acc[m][n][1] + bv.y;
                o1.x = acc[m][n][2] + bv.x;
                o1.y = acc[m][n][3] + bv.y;
                *(float2*)(obase + (size_t)row * N_DIM + col)       = o0;
                *(float2*)(obase + (size_t)(row + 8) * N_DIM + col) = o1;
            }
        }
    }
}

extern "C" void kernel_launch(void* const* d_in, const int* in_sizes, int n_in,
                              void* d_out, int out_size)
{
    const float* x       = (const float*)d_in[0];
    const int*   cat_ids = (const int*)  d_in[1];
    const float* W       = (const float*)d_in[2];
    const float* bias    = (const float*)d_in[3];
    float*       out     = (float*)d_out;

    flag_cats<<<1, 64>>>(cat_ids);
    {
        dim3 wgrid(256, NCAT);     // 256 blocks x 32 cats
        cvt_w<<<wgrid, 256>>>(W);
        cvt_x<<<2048, 256>>>(x);
    }

    cudaFuncSetAttribute(cat_linear_mma, cudaFuncAttributeMaxDynamicSharedMemorySize, SMEM_BYTES);
    dim3 grid(B_DIM, T_DIM / TM, N_DIM / TN);   // (64, 2, 16): bn outermost
    cat_linear_mma<<<grid, NTHREADS, SMEM_BYTES>>>(cat_ids, bias, out);
}

// round 10
// speedup vs baseline: 1.0185x; 1.0185x over previous
#include <cuda_runtime.h>
#include <cuda_fp16.h>
#include <cstdint>

// CategorySpecificLinear, round 10:
//  pass 0: flag used categories
//  pass 1: convert used-category W slices to fp16 scratch
//  pass 2: convert x to fp16 scratch
//  pass 3: GEMM (r8 pipeline: TK=32, NBUF=4, batch-outermost grid) with
//          256 threads/CTA, 64x32 warp tiles -> 4 warps/SMSP latency hiding.
// out[b] = x[b] @ W[cat_ids[b]] + bias[cat_ids[b]]

#define B_DIM 64
#define T_DIM 256
#define K_DIM 1024
#define N_DIM 2048
#define NCAT  32

#define TM 128
#define TN 128
#define TK 32
#define STAGES (K_DIM / TK)      // 32
#define NBUF 4
#define NTHREADS 256

// A tile: 128 rows x 32 k f16 = 64B/row, SW128 swizzled (2 rows / 128B line).
#define A_STAGE_BYTES (128 * 64)             // 8192
// B tile: 32 k-rows x 128 n f16, row = 256B + 16B pad = 272B.
#define B_ROW_BYTES 272
#define B_STAGE_BYTES (32 * B_ROW_BYTES)     // 8704
#define STAGE_BYTES (A_STAGE_BYTES + B_STAGE_BYTES)  // 16896
#define SMEM_BYTES (NBUF * STAGE_BYTES)      // 67584 -> 2 CTAs/SM

__device__ __half g_xh[(size_t)B_DIM * T_DIM * K_DIM];   // 32 MiB
__device__ __half g_wh[(size_t)NCAT * K_DIM * N_DIM];    // 128 MiB
__device__ int    g_catflag[NCAT];

static __device__ __forceinline__ uint32_t sw(uint32_t b) { return b ^ ((b >> 3) & 0x70); }

static __device__ __forceinline__ uint32_t packh2(float lo, float hi) {
    uint32_t r;
    asm("cvt.rn.f16x2.f32 %0, %1, %2;" : "=r"(r) : "f"(hi), "f"(lo));
    return r;
}

static __device__ __forceinline__ void cpasync16(uint32_t dst, const void* src) {
    asm volatile("cp.async.cg.shared.global [%0], [%1], 16;" :: "r"(dst), "l"(src));
}

static __device__ __forceinline__ void ldsm_x4(uint32_t (&r)[4], uint32_t addr) {
    asm volatile("ldmatrix.sync.aligned.m8n8.x4.shared.b16 {%0,%1,%2,%3}, [%4];"
                 : "=r"(r[0]), "=r"(r[1]), "=r"(r[2]), "=r"(r[3]) : "r"(addr));
}
static __device__ __forceinline__ void ldsm_x4_trans(uint32_t (&r)[4], uint32_t addr) {
    asm volatile("ldmatrix.sync.aligned.m8n8.x4.trans.shared.b16 {%0,%1,%2,%3}, [%4];"
                 : "=r"(r[0]), "=r"(r[1]), "=r"(r[2]), "=r"(r[3]) : "r"(addr));
}

static __device__ __forceinline__ void mma_f16(float (&d)[4],
                                               const uint32_t (&a)[4],
                                               const uint32_t* b) {
    asm volatile(
        "mma.sync.aligned.m16n8k16.row.col.f32.f16.f16.f32 "
        "{%0,%1,%2,%3}, {%4,%5,%6,%7}, {%8,%9}, {%0,%1,%2,%3};"
        : "+f"(d[0]), "+f"(d[1]), "+f"(d[2]), "+f"(d[3])
        : "r"(a[0]), "r"(a[1]), "r"(a[2]), "r"(a[3]), "r"(b[0]), "r"(b[1]));
}

// ---------------- pass 0: flag used categories -------------------------------
__global__ void flag_cats(const int* __restrict__ cat_ids)
{
    int tid = threadIdx.x;
    if (tid < NCAT) g_catflag[tid] = 0;
    __syncthreads();
    if (tid < B_DIM) atomicOr(&g_catflag[cat_ids[tid]], 1);
}

// ---------------- pass 1: convert W (skip unused cats) ----------------------
__global__ void __launch_bounds__(256)
cvt_w(const float* __restrict__ W)
{
    const int cat = blockIdx.y;
    if (!g_catflag[cat]) return;
    const float* src = W + (size_t)cat * K_DIM * N_DIM;
    __half* dst = g_wh + (size_t)cat * K_DIM * N_DIM;
    const int n8 = (K_DIM * N_DIM) / 8;                 // 262144
    int i = blockIdx.x * blockDim.x + threadIdx.x;
    const int stride = gridDim.x * blockDim.x;
    for (; i < n8; i += stride) {
        float4 a = ((const float4*)src)[2 * i];
        float4 b = ((const float4*)src)[2 * i + 1];
        uint4 o;
        o.x = packh2(a.x, a.y);
        o.y = packh2(a.z, a.w);
        o.z = packh2(b.x, b.y);
        o.w = packh2(b.z, b.w);
        ((uint4*)dst)[i] = o;
    }
}

// ---------------- pass 2: convert x ------------------------------------------
__global__ void __launch_bounds__(256)
cvt_x(const float* __restrict__ x)
{
    const int n8 = (B_DIM * T_DIM * K_DIM) / 8;         // 2097152
    int i = blockIdx.x * blockDim.x + threadIdx.x;
    const int stride = gridDim.x * blockDim.x;
    for (; i < n8; i += stride) {
        float4 a = ((const float4*)x)[2 * i];
        float4 b = ((const float4*)x)[2 * i + 1];
        uint4 o;
        o.x = packh2(a.x, a.y);
        o.y = packh2(a.z, a.w);
        o.z = packh2(b.x, b.y);
        o.w = packh2(b.z, b.w);
        ((uint4*)g_xh)[i] = o;
    }
}

// ---------------- pass 3: GEMM ------------------------------------------------
__global__ void __launch_bounds__(NTHREADS, 2)
cat_linear_mma(const int* __restrict__ cat_ids,
               const float* __restrict__ bias,
               float* __restrict__ out)
{
    extern __shared__ char smraw[];
    const uint32_t smbase = (uint32_t)__cvta_generic_to_shared(smraw);

    const int tid  = threadIdx.x;
    const int wid  = tid >> 5;
    const int lane = tid & 31;
    const int wm   = wid >> 2;        // 0..1 (M half)
    const int wn   = wid & 3;         // 0..3 (N quarter)
    const int fr   = lane >> 2;       // 0..7
    const int fc   = lane & 3;        // 0..3

    // r8 grid order: bn innermost (x), batch outermost (z) — one batch's 32
    // CTAs run together, sharing one cat's 4 MB W slice in L2.
    const int bn    = blockIdx.x;     // 0..15
    const int bm    = blockIdx.y;     // 0..1
    const int batch = blockIdx.z;     // 0..63
    const int n0    = bn * TN;
    const int cat   = cat_ids[batch];

    const __half* Ap = g_xh + (size_t)batch * T_DIM * K_DIM + (size_t)bm * TM * K_DIM;
    const __half* Bp = g_wh + (size_t)cat * K_DIM * N_DIM + n0;

    // cp.async maps (16B granules), 256 threads:
    // A: 512 chunks = 128 rows x 4; thread i: f=tid+256i -> m=f>>2, c=f&3
    // B: 512 chunks = 32 rows x 16; thread i: f=tid+256i -> k=f>>4, c=f&15
    // ldmatrix per-lane address components
    const int q_row = (lane & 7) + 8 * ((lane >> 3) & 1);
    const int q_hi  = (lane >> 4);
    const uint32_t a_pre = (uint32_t)((wm * 64 + q_row) * 64 + 16 * q_hi);
    const uint32_t b_pre = (uint32_t)(q_row * B_ROW_BYTES + (wn * 32 + 8 * q_hi) * 2);

    float acc[4][4][4];
#pragma unroll
    for (int m = 0; m < 4; m++)
#pragma unroll
        for (int n = 0; n < 4; n++)
#pragma unroll
            for (int j = 0; j < 4; j++) acc[m][n][j] = 0.f;

    auto issue_stage = [&](int s, int buf) {
        const uint32_t abase = smbase + (uint32_t)buf * STAGE_BYTES;
        const uint32_t bbase = abase + A_STAGE_BYTES;
        const int k0 = s * TK;
#pragma unroll
        for (int i = 0; i < 2; i++) {
            int f = tid + NTHREADS * i;
            int m = f >> 2, c = f & 3;
            cpasync16(abase + sw((uint32_t)m * 64u + (uint32_t)c * 16u),
                      Ap + (size_t)m * K_DIM + k0 + c * 8);
        }
#pragma unroll
        for (int i = 0; i < 2; i++) {
            int f = tid + NTHREADS * i;
            int k = f >> 4, c = f & 15;
            cpasync16(bbase + (uint32_t)k * B_ROW_BYTES + (uint32_t)c * 16u,
                      Bp + (size_t)(k0 + k) * N_DIM + c * 8);
        }
    };

    // prologue: 3 stages in flight
    issue_stage(0, 0);
    asm volatile("cp.async.commit_group;" ::: "memory");
    issue_stage(1, 1);
    asm volatile("cp.async.commit_group;" ::: "memory");
    issue_stage(2, 2);
    asm volatile("cp.async.commit_group;" ::: "memory");

    for (int s = 0; s < STAGES; s++) {
        asm volatile("cp.async.wait_group 2;" ::: "memory");
        __syncthreads();

        // refill: buffer (s+3)%4 held stage s-1, done by all warps at barrier
        if (s + 3 < STAGES)
            issue_stage(s + 3, (s + 3) % NBUF);
        asm volatile("cp.async.commit_group;" ::: "memory");

        const uint32_t abase = smbase + (uint32_t)(s % NBUF) * STAGE_BYTES;
        const uint32_t bbase = abase + A_STAGE_BYTES;

#pragma unroll
        for (int kb = 0; kb < TK; kb += 16) {
            uint32_t af[4][4], bf[2][4];
#pragma unroll
            for (int mt = 0; mt < 4; mt++)
                ldsm_x4(af[mt], abase + sw(a_pre + (uint32_t)(mt * 16 * 64) + (uint32_t)(kb * 2)));
#pragma unroll
            for (int g = 0; g < 2; g++)
                ldsm_x4_trans(bf[g], bbase + b_pre + (uint32_t)(kb * B_ROW_BYTES) + (uint32_t)(g * 32));
#pragma unroll
            for (int m = 0; m < 4; m++)
#pragma unroll
                for (int n = 0; n < 4; n++)
                    mma_f16(acc[m][n], af[m], &bf[n >> 1][(n & 1) * 2]);
        }
    }

    // epilogue: add bias, store
    {
        const float* brow = bias + (size_t)cat * N_DIM;
        float* obase = out + (size_t)batch * T_DIM * N_DIM;
#pragma unroll
        for (int m = 0; m < 4; m++) {
            int row = bm * TM + wm * 64 + m * 16 + fr;
#pragma unroll
            for (int n = 0; n < 4; n++) {
                int col = n0 + wn * 32 + n * 8 + fc * 2;
                float2 bv = *(const float2*)(brow + col);
                float2 o0, o1;
                o0.x = acc[m][n][0] + bv.x;
                o0.y = acc[m][n][1] + bv.y;
                o1.x = acc[m][n][2] + bv.x;
                o1.y = acc[m][n][3] + bv.y;
                *(float2*)(obase + (size_t)row * N_DIM + col)       = o0;
                *(float2*)(obase + (size_t)(row + 8) * N_DIM + col) = o1;
            }
        }
    }
}

extern "C" void kernel_launch(void* const* d_in, const int* in_sizes, int n_in,
                              void* d_out, int out_size)
{
    const float* x       = (const float*)d_in[0];
    const int*   cat_ids = (const int*)  d_in[1];
    const float* W       = (const float*)d_in[2];
    const float* bias    = (const float*)d_in[3];
    float*       out     = (float*)d_out;

    flag_cats<<<1, 64>>>(cat_ids);
    {
        dim3 wgrid(256, NCAT);     // 256 blocks x 32 cats (skip unused)
        cvt_w<<<wgrid, 256>>>(W);
        cvt_x<<<2048, 256>>>(x);
    }

    cudaFuncSetAttribute(cat_linear_mma, cudaFuncAttributeMaxDynamicSharedMemorySize, SMEM_BYTES);
    dim3 grid(N_DIM / TN, T_DIM / TM, B_DIM);   // (16, 2, 64): batch outermost
    cat_linear_mma<<<grid, NTHREADS, SMEM_BYTES>>>(cat_ids, bias, out);
}

// round 11
// speedup vs baseline: 1.1093x; 1.0892x over previous
#include <cuda_runtime.h>
#include <cuda_fp16.h>
#include <cstdint>

// CategorySpecificLinear, round 11 = r8's GEMM (best measured: ~154us)
//                                  + r9's cat-skip converters.
//  pass 0: flag used categories
//  pass 1: convert used-category W slices to fp16 scratch
//  pass 2: convert x to fp16 scratch
//  pass 3: GEMM: cp.async fp16 4-stage ring (TK=32), 128 thr, 64x64 warp
//          tiles, ldmatrix + mma m16n8k16, batch-outermost grid.
// out[b] = x[b] @ W[cat_ids[b]] + bias[cat_ids[b]]

#define B_DIM 64
#define T_DIM 256
#define K_DIM 1024
#define N_DIM 2048
#define NCAT  32

#define TM 128
#define TN 128
#define TK 32
#define STAGES (K_DIM / TK)      // 32
#define NBUF 4
#define NTHREADS 128

// A tile: 128 rows x 32 k f16 = 64B/row, SW128 swizzled.
#define A_STAGE_BYTES (128 * 64)             // 8192
// B tile: 32 k-rows x 128 n f16, row = 256B + 16B pad = 272B.
#define B_ROW_BYTES 272
#define B_STAGE_BYTES (32 * B_ROW_BYTES)     // 8704
#define STAGE_BYTES (A_STAGE_BYTES + B_STAGE_BYTES)  // 16896
#define SMEM_BYTES (NBUF * STAGE_BYTES)      // 67584 -> 2 CTAs/SM

__device__ __half g_xh[(size_t)B_DIM * T_DIM * K_DIM];   // 32 MiB
__device__ __half g_wh[(size_t)NCAT * K_DIM * N_DIM];    // 128 MiB
__device__ int    g_catflag[NCAT];

static __device__ __forceinline__ uint32_t sw(uint32_t b) { return b ^ ((b >> 3) & 0x70); }

static __device__ __forceinline__ uint32_t packh2(float lo, float hi) {
    uint32_t r;
    asm("cvt.rn.f16x2.f32 %0, %1, %2;" : "=r"(r) : "f"(hi), "f"(lo));
    return r;
}

static __device__ __forceinline__ void cpasync16(uint32_t dst, const void* src) {
    asm volatile("cp.async.cg.shared.global [%0], [%1], 16;" :: "r"(dst), "l"(src));
}

static __device__ __forceinline__ void ldsm_x4(uint32_t (&r)[4], uint32_t addr) {
    asm volatile("ldmatrix.sync.aligned.m8n8.x4.shared.b16 {%0,%1,%2,%3}, [%4];"
                 : "=r"(r[0]), "=r"(r[1]), "=r"(r[2]), "=r"(r[3]) : "r"(addr));
}
static __device__ __forceinline__ void ldsm_x4_trans(uint32_t (&r)[4], uint32_t addr) {
    asm volatile("ldmatrix.sync.aligned.m8n8.x4.trans.shared.b16 {%0,%1,%2,%3}, [%4];"
                 : "=r"(r[0]), "=r"(r[1]), "=r"(r[2]), "=r"(r[3]) : "r"(addr));
}

static __device__ __forceinline__ void mma_f16(float (&d)[4],
                                               const uint32_t (&a)[4],
                                               const uint32_t* b) {
    asm volatile(
        "mma.sync.aligned.m16n8k16.row.col.f32.f16.f16.f32 "
        "{%0,%1,%2,%3}, {%4,%5,%6,%7}, {%8,%9}, {%0,%1,%2,%3};"
        : "+f"(d[0]), "+f"(d[1]), "+f"(d[2]), "+f"(d[3])
        : "r"(a[0]), "r"(a[1]), "r"(a[2]), "r"(a[3]), "r"(b[0]), "r"(b[1]));
}

// ---------------- pass 0: flag used categories -------------------------------
__global__ void flag_cats(const int* __restrict__ cat_ids)
{
    int tid = threadIdx.x;
    if (tid < NCAT) g_catflag[tid] = 0;
    __syncthreads();
    if (tid < B_DIM) atomicOr(&g_catflag[cat_ids[tid]], 1);
}

// ---------------- pass 1: convert W (skip unused cats) ----------------------
__global__ void __launch_bounds__(256)
cvt_w(const float* __restrict__ W)
{
    const int cat = blockIdx.y;
    if (!g_catflag[cat]) return;
    const float* src = W + (size_t)cat * K_DIM * N_DIM;
    __half* dst = g_wh + (size_t)cat * K_DIM * N_DIM;
    const int n8 = (K_DIM * N_DIM) / 8;                 // 262144
    int i = blockIdx.x * blockDim.x + threadIdx.x;
    const int stride = gridDim.x * blockDim.x;
    for (; i < n8; i += stride) {
        float4 a = ((const float4*)src)[2 * i];
        float4 b = ((const float4*)src)[2 * i + 1];
        uint4 o;
        o.x = packh2(a.x, a.y);
        o.y = packh2(a.z, a.w);
        o.z = packh2(b.x, b.y);
        o.w = packh2(b.z, b.w);
        ((uint4*)dst)[i] = o;
    }
}

// ---------------- pass 2: convert x ------------------------------------------
__global__ void __launch_bounds__(256)
cvt_x(const float* __restrict__ x)
{
    const int n8 = (B_DIM * T_DIM * K_DIM) / 8;         // 2097152
    int i = blockIdx.x * blockDim.x + threadIdx.x;
    const int stride = gridDim.x * blockDim.x;
    for (; i < n8; i += stride) {
        float4 a = ((const float4*)x)[2 * i];
        float4 b = ((const float4*)x)[2 * i + 1];
        uint4 o;
        o.x = packh2(a.x, a.y);
        o.y = packh2(a.z, a.w);
        o.z = packh2(b.x, b.y);
        o.w = packh2(b.z, b.w);
        ((uint4*)g_xh)[i] = o;
    }
}

// ---------------- pass 3: GEMM (exact round-8 configuration) ----------------
__global__ void __launch_bounds__(NTHREADS, 2)
cat_linear_mma(const int* __restrict__ cat_ids,
               const float* __restrict__ bias,
               float* __restrict__ out)
{
    extern __shared__ char smraw[];
    const uint32_t smbase = (uint32_t)__cvta_generic_to_shared(smraw);

    const int tid  = threadIdx.x;
    const int wid  = tid >> 5;
    const int lane = tid & 31;
    const int wm   = wid >> 1;        // 0..1 (M half)
    const int wn   = wid & 1;         // 0..1 (N half)
    const int fr   = lane >> 2;       // 0..7
    const int fc   = lane & 3;        // 0..3

    const int bn    = blockIdx.x;     // 0..15
    const int bm    = blockIdx.y;     // 0..1
    const int batch = blockIdx.z;     // 0..63
    const int n0    = bn * TN;
    const int cat   = cat_ids[batch];

    const __half* Ap = g_xh + (size_t)batch * T_DIM * K_DIM + (size_t)bm * TM * K_DIM;
    const __half* Bp = g_wh + (size_t)cat * K_DIM * N_DIM + n0;

    // cp.async maps (16B granules):
    // A: 512 chunks = 128 rows x 4; thread: m=(tid>>2)+32i, c=tid&3
    const int am0 = tid >> 2;
    const int acx = tid & 3;
    // B: 512 chunks = 32 rows x 16; thread: k=(tid>>4)+8i, c=tid&15
    const int bk0 = tid >> 4;
    const int bcx = tid & 15;

    // ldmatrix per-lane address components
    const int q_row = (lane & 7) + 8 * ((lane >> 3) & 1);
    const int q_hi  = (lane >> 4);
    const uint32_t a_pre = (uint32_t)((wm * 64 + q_row) * 64 + 16 * q_hi);
    const uint32_t b_pre = (uint32_t)(q_row * B_ROW_BYTES + (wn * 64 + 8 * q_hi) * 2);

    float acc[4][8][4];
#pragma unroll
    for (int m = 0; m < 4; m++)
#pragma unroll
        for (int n = 0; n < 8; n++)
#pragma unroll
            for (int j = 0; j < 4; j++) acc[m][n][j] = 0.f;

    auto issue_stage = [&](int s, int buf) {
        const uint32_t abase = smbase + (uint32_t)buf * STAGE_BYTES;
        const uint32_t bbase = abase + A_STAGE_BYTES;
        const int k0 = s * TK;
#pragma unroll
        for (int i = 0; i < 4; i++) {
            int m = am0 + 32 * i;
            cpasync16(abase + sw((uint32_t)m * 64u + (uint32_t)acx * 16u),
                      Ap + (size_t)m * K_DIM + k0 + acx * 8);
        }
#pragma unroll
        for (int i = 0; i < 4; i++) {
            int k = bk0 + 8 * i;
            cpasync16(bbase + (uint32_t)k * B_ROW_BYTES + (uint32_t)bcx * 16u,
                      Bp + (size_t)(k0 + k) * N_DIM + bcx * 8);
        }
    };

    // prologue: 3 stages in flight
    issue_stage(0, 0);
    asm volatile("cp.async.commit_group;" ::: "memory");
    issue_stage(1, 1);
    asm volatile("cp.async.commit_group;" ::: "memory");
    issue_stage(2, 2);
    asm volatile("cp.async.commit_group;" ::: "memory");

    for (int s = 0; s < STAGES; s++) {
        asm volatile("cp.async.wait_group 2;" ::: "memory");
        __syncthreads();

        // refill: buffer (s+3)%4 held stage s-1, done by all warps at barrier
        if (s + 3 < STAGES)
            issue_stage(s + 3, (s + 3) % NBUF);
        asm volatile("cp.async.commit_group;" ::: "memory");

        const uint32_t abase = smbase + (uint32_t)(s % NBUF) * STAGE_BYTES;
        const uint32_t bbase = abase + A_STAGE_BYTES;

#pragma unroll
        for (int kb = 0; kb < TK; kb += 16) {
            uint32_t af[4][4], bf[4][4];
#pragma unroll
            for (int mt = 0; mt < 4; mt++)
                ldsm_x4(af[mt], abase + sw(a_pre + (uint32_t)(mt * 16 * 64) + (uint32_t)(kb * 2)));
#pragma unroll
            for (int g = 0; g < 4; g++)
                ldsm_x4_trans(bf[g], bbase + b_pre + (uint32_t)(kb * B_ROW_BYTES) + (uint32_t)(g * 32));
#pragma unroll
            for (int m = 0; m < 4; m++)
#pragma unroll
                for (int n = 0; n < 8; n++)
                    mma_f16(acc[m][n], af[m], &bf[n >> 1][(n & 1) * 2]);
        }
    }

    // epilogue: add bias, store
    {
        const float* brow = bias + (size_t)cat * N_DIM;
        float* obase = out + (size_t)batch * T_DIM * N_DIM;
#pragma unroll
        for (int m = 0; m < 4; m++) {
            int row = bm * TM + wm * 64 + m * 16 + fr;
#pragma unroll
            for (int n = 0; n < 8; n++) {
                int col = n0 + wn * 64 + n * 8 + fc * 2;
                float2 bv = *(const float2*)(brow + col);
                float2 o0, o1;
                o0.x = acc[m][n][0] + bv.x;
                o0.y = acc[m][n][1] + bv.y;
                o1.x = acc[m][n][2] + bv.x;
                o1.y = acc[m][n][3] + bv.y;
                *(float2*)(obase + (size_t)row * N_DIM + col)       = o0;
                *(float2*)(obase + (size_t)(row + 8) * N_DIM + col) = o1;
            }
        }
    }
}

extern "C" void kernel_launch(void* const* d_in, const int* in_sizes, int n_in,
                              void* d_out, int out_size)
{
    const float* x       = (const float*)d_in[0];
    const int*   cat_ids = (const int*)  d_in[1];
    const float* W       = (const float*)d_in[2];
    const float* bias    = (const float*)d_in[3];
    float*       out     = (float*)d_out;

    flag_cats<<<1, 64>>>(cat_ids);
    {
        dim3 wgrid(256, NCAT);     // 256 blocks x 32 cats (skip unused)
        cvt_w<<<wgrid, 256>>>(W);
        cvt_x<<<2048, 256>>>(x);
    }

    cudaFuncSetAttribute(cat_linear_mma, cudaFuncAttributeMaxDynamicSharedMemorySize, SMEM_BYTES);
    dim3 grid(N_DIM / TN, T_DIM / TM, B_DIM);   // (16, 2, 64): batch outermost
    cat_linear_mma<<<grid, NTHREADS, SMEM_BYTES>>>(cat_ids, bias, out);
}